// round 14
// baseline (speedup 1.0000x reference)
#include <cuda_runtime.h>
#include <cuda_bf16.h>
#include <math.h>
#include <float.h>
#include <stdint.h>

// Problem constants
constexpr int CB  = 2;
constexpr int CS  = 2048;
constexpr int CE  = 2048;
constexpr int CH  = 16;
constexpr int CKV = 8;
constexpr int CD  = 128;
constexpr int MROWS = CB * CS;          // 4096
constexpr int KVD   = CKV * CD;         // 1024
constexpr float RMS_EPS = 1.1920928955078125e-07f;
constexpr float ATTN_SCALE = 0.08838834764831845f;  // 1/sqrt(128)

// Scratch (device globals; no runtime allocation allowed)
__device__ float g_q[MROWS * CE];
__device__ float g_k[MROWS * KVD];
__device__ float g_v[MROWS * KVD];
__device__ float g_attn[MROWS * CE];

// ---------------------------------------------------------------------------
// Helpers: bf16 hi/lo split + bf16 mma.sync
// ---------------------------------------------------------------------------
__device__ __forceinline__ void split2(float a, float b, uint32_t& hi, uint32_t& lo)
{
    __nv_bfloat16 ha = __float2bfloat16(a);
    __nv_bfloat16 hb = __float2bfloat16(b);
    float fa = __bfloat162float(ha), fb = __bfloat162float(hb);
    __nv_bfloat16 la = __float2bfloat16(a - fa);
    __nv_bfloat16 lb = __float2bfloat16(b - fb);
    hi = (uint32_t)__bfloat16_as_ushort(ha) | ((uint32_t)__bfloat16_as_ushort(hb) << 16);
    lo = (uint32_t)__bfloat16_as_ushort(la) | ((uint32_t)__bfloat16_as_ushort(lb) << 16);
}

__device__ __forceinline__ void mma_bf16(float (&c)[4],
    uint32_t a0, uint32_t a1, uint32_t a2, uint32_t a3,
    uint32_t b0, uint32_t b1)
{
    asm volatile(
        "mma.sync.aligned.m16n8k16.row.col.f32.bf16.bf16.f32 "
        "{%0,%1,%2,%3},{%4,%5,%6,%7},{%8,%9},{%0,%1,%2,%3};"
        : "+f"(c[0]), "+f"(c[1]), "+f"(c[2]), "+f"(c[3])
        : "r"(a0), "r"(a1), "r"(a2), "r"(a3), "r"(b0), "r"(b1));
}

// ---------------------------------------------------------------------------
// 3xBF16 tensor-core GEMM: C[M,N] = A[M,K] @ W[N,K]^T + bias[N]
// Block tile 128x128, BK=16, 256 threads (8 warps 2x4), warp tile 64x32.
// 3-stage smem pipeline, single __syncthreads per k-step; the LDG for
// k-step ks+2 is issued one full iteration before its split+store.
// ---------------------------------------------------------------------------
constexpr int SW     = 12;              // smem row stride in words (8 used + 4 pad)
constexpr int TILEW  = 128 * SW;        // 1536 words per tile
constexpr int STAGEW = 4 * TILEW;       // Ahi, Alo, Whi, Wlo = 6144 words
constexpr int NSTG   = 3;
constexpr int GEMM_SMEM = NSTG * STAGEW * 4;  // 73728 B

__device__ __forceinline__ void gemm_store_stage(
    uint32_t* st, int o0, int o1,
    const float4& ra0, const float4& ra1, const float4& rw0, const float4& rw1)
{
    uint32_t* hA = st;
    uint32_t* lA = st + TILEW;
    uint32_t* hW = st + 2 * TILEW;
    uint32_t* lW = st + 3 * TILEW;
    uint32_t h0, l0, h1, l1;
    split2(ra0.x, ra0.y, h0, l0); split2(ra0.z, ra0.w, h1, l1);
    hA[o0] = h0; hA[o0 + 1] = h1; lA[o0] = l0; lA[o0 + 1] = l1;
    split2(ra1.x, ra1.y, h0, l0); split2(ra1.z, ra1.w, h1, l1);
    hA[o1] = h0; hA[o1 + 1] = h1; lA[o1] = l0; lA[o1 + 1] = l1;
    split2(rw0.x, rw0.y, h0, l0); split2(rw0.z, rw0.w, h1, l1);
    hW[o0] = h0; hW[o0 + 1] = h1; lW[o0] = l0; lW[o0 + 1] = l1;
    split2(rw1.x, rw1.y, h0, l0); split2(rw1.z, rw1.w, h1, l1);
    hW[o1] = h0; hW[o1 + 1] = h1; lW[o1] = l0; lW[o1 + 1] = l1;
}

__global__ __launch_bounds__(256) void gemm_bf16x3_nt_bias(
    const float* __restrict__ A, const float* __restrict__ W,
    const float* __restrict__ bias, float* __restrict__ C,
    int Ndim, int Kdim)
{
    extern __shared__ uint32_t smw[];
    const int tid  = threadIdx.x;
    const int warp = tid >> 5, lane = tid & 31;
    const int wm = warp & 1, wn = warp >> 1;
    const int grp = lane >> 2, qd = lane & 3;
    const int row0 = blockIdx.y * 128;
    const int col0 = blockIdx.x * 128;

    const int ar = tid >> 2;             // 0..63 (rows ar, ar+64)
    const int kq = (tid & 3) << 2;       // 0,4,8,12
    const int kw = kq >> 1;              // word offset 0,2,4,6
    const float* Ap = A + (size_t)row0 * Kdim;
    const float* Wp = W + (size_t)col0 * Kdim;
    const int o0 = ar * SW + kw;
    const int o1 = (ar + 64) * SW + kw;

    float acc[4][4][4];
    #pragma unroll
    for (int i = 0; i < 4; i++)
        #pragma unroll
        for (int j = 0; j < 4; j++)
            #pragma unroll
            for (int c = 0; c < 4; c++) acc[i][j][c] = 0.f;

    const int NK = Kdim / 16;
    float4 ra0, ra1, rw0, rw1;

    // prologue: k0 -> stage 0; k1 -> regs
    ra0 = *(const float4*)&Ap[(size_t)ar * Kdim + kq];
    ra1 = *(const float4*)&Ap[(size_t)(ar + 64) * Kdim + kq];
    rw0 = *(const float4*)&Wp[(size_t)ar * Kdim + kq];
    rw1 = *(const float4*)&Wp[(size_t)(ar + 64) * Kdim + kq];
    gemm_store_stage(smw, o0, o1, ra0, ra1, rw0, rw1);
    if (NK > 1) {
        ra0 = *(const float4*)&Ap[(size_t)ar * Kdim + 16 + kq];
        ra1 = *(const float4*)&Ap[(size_t)(ar + 64) * Kdim + 16 + kq];
        rw0 = *(const float4*)&Wp[(size_t)ar * Kdim + 16 + kq];
        rw1 = *(const float4*)&Wp[(size_t)(ar + 64) * Kdim + 16 + kq];
    }
    __syncthreads();

    int stg_store = 1;   // stage for k-step ks+1
    int stg_comp  = 0;   // stage for k-step ks

    for (int ks = 0; ks < NK; ks++) {
        // store regs (k-step ks+1, loaded last iter) into its stage
        if (ks + 1 < NK)
            gemm_store_stage(smw + stg_store * STAGEW, o0, o1, ra0, ra1, rw0, rw1);

        // issue LDG for k-step ks+2 (consumed next iteration)
        if (ks + 2 < NK) {
            const int k0 = (ks + 2) * 16;
            ra0 = *(const float4*)&Ap[(size_t)ar * Kdim + k0 + kq];
            ra1 = *(const float4*)&Ap[(size_t)(ar + 64) * Kdim + k0 + kq];
            rw0 = *(const float4*)&Wp[(size_t)ar * Kdim + k0 + kq];
            rw1 = *(const float4*)&Wp[(size_t)(ar + 64) * Kdim + k0 + kq];
        }

        // compute on stage stg_comp
        {
            const uint32_t* st = smw + stg_comp * STAGEW;
            const uint32_t* uAh = st;
            const uint32_t* uAl = st + TILEW;
            const uint32_t* uWh = st + 2 * TILEW;
            const uint32_t* uWl = st + 3 * TILEW;

            uint32_t ah[4][4], al[4][4], bh[4][2], bl[4][2];
            #pragma unroll
            for (int mt = 0; mt < 4; mt++) {
                const int m = wm * 64 + mt * 16;
                const int a0o = (m + grp) * SW + qd;
                const int a1o = a0o + 8 * SW;
                ah[mt][0] = uAh[a0o]; ah[mt][1] = uAh[a1o];
                ah[mt][2] = uAh[a0o + 4]; ah[mt][3] = uAh[a1o + 4];
                al[mt][0] = uAl[a0o]; al[mt][1] = uAl[a1o];
                al[mt][2] = uAl[a0o + 4]; al[mt][3] = uAl[a1o + 4];
            }
            #pragma unroll
            for (int nt = 0; nt < 4; nt++) {
                const int bo = (wn * 32 + nt * 8 + grp) * SW + qd;
                bh[nt][0] = uWh[bo]; bh[nt][1] = uWh[bo + 4];
                bl[nt][0] = uWl[bo]; bl[nt][1] = uWl[bo + 4];
            }
            #pragma unroll
            for (int mt = 0; mt < 4; mt++)
                #pragma unroll
                for (int nt = 0; nt < 4; nt++)
                    mma_bf16(acc[mt][nt], ah[mt][0], ah[mt][1], ah[mt][2], ah[mt][3],
                             bh[nt][0], bh[nt][1]);
            #pragma unroll
            for (int mt = 0; mt < 4; mt++)
                #pragma unroll
                for (int nt = 0; nt < 4; nt++)
                    mma_bf16(acc[mt][nt], ah[mt][0], ah[mt][1], ah[mt][2], ah[mt][3],
                             bl[nt][0], bl[nt][1]);
            #pragma unroll
            for (int mt = 0; mt < 4; mt++)
                #pragma unroll
                for (int nt = 0; nt < 4; nt++)
                    mma_bf16(acc[mt][nt], al[mt][0], al[mt][1], al[mt][2], al[mt][3],
                             bh[nt][0], bh[nt][1]);
        }

        stg_comp  = (stg_comp  + 1 == NSTG) ? 0 : stg_comp + 1;
        stg_store = (stg_store + 1 == NSTG) ? 0 : stg_store + 1;
        __syncthreads();
    }

    #pragma unroll
    for (int mt = 0; mt < 4; mt++) {
        const int row = row0 + wm * 64 + mt * 16 + grp;
        #pragma unroll
        for (int nt = 0; nt < 4; nt++) {
            const int col = col0 + wn * 32 + nt * 8 + 2 * qd;
            const float b0 = bias[col], b1 = bias[col + 1];
            float2 v0, v1;
            v0.x = acc[mt][nt][0] + b0; v0.y = acc[mt][nt][1] + b1;
            v1.x = acc[mt][nt][2] + b0; v1.y = acc[mt][nt][3] + b1;
            *(float2*)&C[(size_t)row * Ndim + col] = v0;
            *(float2*)&C[(size_t)(row + 8) * Ndim + col] = v1;
        }
    }
}

// ---------------------------------------------------------------------------
// RMSNorm over contiguous 128-element segments.
// ---------------------------------------------------------------------------
__global__ __launch_bounds__(128) void rmsnorm_kernel(
    float* __restrict__ buf, const float* __restrict__ w)
{
    __shared__ float red[4];
    float* p = buf + (size_t)blockIdx.x * CD;
    const int t = threadIdx.x;
    float v = p[t];
    float sq = v * v;
    #pragma unroll
    for (int o = 16; o > 0; o >>= 1) sq += __shfl_xor_sync(0xffffffffu, sq, o);
    if ((t & 31) == 0) red[t >> 5] = sq;
    __syncthreads();
    float ms = (red[0] + red[1] + red[2] + red[3]) * (1.0f / 128.0f);
    p[t] = v * rsqrtf(ms + RMS_EPS) * w[t];
}

// ---------------------------------------------------------------------------
// Flash attention, bf16x3 tensor cores (R11 version). 128-query blocks,
// 128-key tiles as two 64-key halves. 256 threads, qt reversed.
// ---------------------------------------------------------------------------
constexpr int QSW = 68;
constexpr int VSW = 68;
constexpr int OFF_QH = 0;
constexpr int OFF_QL = OFF_QH + 128 * QSW;
constexpr int OFF_KH = OFF_QL + 128 * QSW;
constexpr int OFF_KL = OFF_KH + 128 * QSW;
constexpr int OFF_VH = OFF_KL + 128 * QSW;
constexpr int OFF_VL = OFF_VH + 128 * VSW;
constexpr int FLASH_WORDS = OFF_VL + 128 * VSW;
constexpr int FLASH_SMEM = FLASH_WORDS * 4;   // 208896 B

__global__ __launch_bounds__(256) void flash_attn_mma(
    const float* __restrict__ Q, const float* __restrict__ K,
    const float* __restrict__ V, float* __restrict__ O)
{
    extern __shared__ uint32_t swd[];
    uint32_t* sQh = swd + OFF_QH;
    uint32_t* sQl = swd + OFF_QL;
    uint32_t* sKh = swd + OFF_KH;
    uint32_t* sKl = swd + OFF_KL;
    uint32_t* sVh = swd + OFF_VH;
    uint32_t* sVl = swd + OFF_VL;

    const int qt = gridDim.x - 1 - blockIdx.x;
    const int h  = blockIdx.y;
    const int bb = blockIdx.z;
    const int kvh = h >> 1;
    const int tid = threadIdx.x;
    const int warp = tid >> 5, lane = tid & 31;
    const int grp = lane >> 2, qd = lane & 3;
    const int q0 = qt * 128;
    const int rA = warp * 16 + grp;

    for (int i = tid; i < 128 * 64; i += 256) {
        const int r = i >> 6, wd = i & 63;
        float2 f = *(const float2*)&Q[((size_t)(bb * CS + q0 + r)) * CE + h * CD + 2 * wd];
        split2(f.x, f.y, sQh[r * QSW + wd], sQl[r * QSW + wd]);
    }

    float o[16][4];
    #pragma unroll
    for (int nt = 0; nt < 16; nt++)
        #pragma unroll
        for (int c = 0; c < 4; c++) o[nt][c] = 0.f;
    float m0 = -INFINITY, m1 = -INFINITY, l0 = 0.f, l1 = 0.f;

    const int nkt = qt + 1;

    for (int kt = 0; kt < nkt; kt++) {
        const int k0 = kt * 128;
        const bool diag = (kt == nkt - 1);
        __syncthreads();

        for (int i = tid; i < 128 * 64; i += 256) {
            const int r = i >> 6, wd = i & 63;
            float2 f = *(const float2*)&K[((size_t)(bb * CS + k0 + r)) * KVD + kvh * CD + 2 * wd];
            split2(f.x, f.y, sKh[r * QSW + wd], sKl[r * QSW + wd]);
        }
        for (int i = tid; i < 128 * 64; i += 256) {
            const int d = i & 127, j = i >> 7;
            const size_t base = ((size_t)(bb * CS + k0 + 2 * j)) * KVD + kvh * CD + d;
            split2(V[base], V[base + KVD], sVh[d * VSW + j], sVl[d * VSW + j]);
        }
        __syncthreads();

        #pragma unroll
        for (int hh = 0; hh < 2; hh++) {
            float s[8][4];
            #pragma unroll
            for (int nt = 0; nt < 8; nt++)
                #pragma unroll
                for (int c = 0; c < 4; c++) s[nt][c] = 0.f;

            #pragma unroll
            for (int ks = 0; ks < 8; ks++) {
                const int ao  = rA * QSW + ks * 8 + qd;
                const int a1o = ao + 8 * QSW;
                const uint32_t ah0 = sQh[ao],  ah1 = sQh[a1o];
                const uint32_t ah2 = sQh[ao + 4], ah3 = sQh[a1o + 4];
                const uint32_t al0 = sQl[ao],  al1 = sQl[a1o];
                const uint32_t al2 = sQl[ao + 4], al3 = sQl[a1o + 4];
                #pragma unroll
                for (int nt = 0; nt < 8; nt++) {
                    const int bo = (hh * 64 + nt * 8 + grp) * QSW + ks * 8 + qd;
                    const uint32_t bh0 = sKh[bo], bh1 = sKh[bo + 4];
                    const uint32_t bl0 = sKl[bo], bl1 = sKl[bo + 4];
                    mma_bf16(s[nt], ah0, ah1, ah2, ah3, bh0, bh1);
                    mma_bf16(s[nt], ah0, ah1, ah2, ah3, bl0, bl1);
                    mma_bf16(s[nt], al0, al1, al2, al3, bh0, bh1);
                }
            }

            const int gr0 = q0 + rA, gr1 = gr0 + 8;
            if (diag) {
                #pragma unroll
                for (int nt = 0; nt < 8; nt++) {
                    const int gc = k0 + hh * 64 + nt * 8 + 2 * qd;
                    s[nt][0] = (gc     > gr0) ? -1e30f : s[nt][0] * ATTN_SCALE;
                    s[nt][1] = (gc + 1 > gr0) ? -1e30f : s[nt][1] * ATTN_SCALE;
                    s[nt][2] = (gc     > gr1) ? -1e30f : s[nt][2] * ATTN_SCALE;
                    s[nt][3] = (gc + 1 > gr1) ? -1e30f : s[nt][3] * ATTN_SCALE;
                }
            } else {
                #pragma unroll
                for (int nt = 0; nt < 8; nt++) {
                    s[nt][0] *= ATTN_SCALE; s[nt][1] *= ATTN_SCALE;
                    s[nt][2] *= ATTN_SCALE; s[nt][3] *= ATTN_SCALE;
                }
            }

            float mx0 = -INFINITY, mx1 = -INFINITY;
            #pragma unroll
            for (int nt = 0; nt < 8; nt++) {
                mx0 = fmaxf(mx0, fmaxf(s[nt][0], s[nt][1]));
                mx1 = fmaxf(mx1, fmaxf(s[nt][2], s[nt][3]));
            }
            mx0 = fmaxf(mx0, __shfl_xor_sync(0xffffffffu, mx0, 1));
            mx0 = fmaxf(mx0, __shfl_xor_sync(0xffffffffu, mx0, 2));
            mx1 = fmaxf(mx1, __shfl_xor_sync(0xffffffffu, mx1, 1));
            mx1 = fmaxf(mx1, __shfl_xor_sync(0xffffffffu, mx1, 2));
            const float mn0 = fmaxf(m0, mx0), mn1 = fmaxf(m1, mx1);
            const float c0 = __expf(m0 - mn0), c1 = __expf(m1 - mn1);
            float rs0 = 0.f, rs1 = 0.f;
            #pragma unroll
            for (int nt = 0; nt < 8; nt++) {
                s[nt][0] = __expf(s[nt][0] - mn0); rs0 += s[nt][0];
                s[nt][1] = __expf(s[nt][1] - mn0); rs0 += s[nt][1];
                s[nt][2] = __expf(s[nt][2] - mn1); rs1 += s[nt][2];
                s[nt][3] = __expf(s[nt][3] - mn1); rs1 += s[nt][3];
            }
            rs0 += __shfl_xor_sync(0xffffffffu, rs0, 1);
            rs0 += __shfl_xor_sync(0xffffffffu, rs0, 2);
            rs1 += __shfl_xor_sync(0xffffffffu, rs1, 1);
            rs1 += __shfl_xor_sync(0xffffffffu, rs1, 2);
            l0 = l0 * c0 + rs0; l1 = l1 * c1 + rs1;
            m0 = mn0; m1 = mn1;
            #pragma unroll
            for (int nt = 0; nt < 16; nt++) {
                o[nt][0] *= c0; o[nt][1] *= c0;
                o[nt][2] *= c1; o[nt][3] *= c1;
            }

            #pragma unroll
            for (int ks = 0; ks < 4; ks++) {
                uint32_t pa0h, pa0l, pa1h, pa1l, pa2h, pa2l, pa3h, pa3l;
                split2(s[2 * ks][0],     s[2 * ks][1],     pa0h, pa0l);
                split2(s[2 * ks][2],     s[2 * ks][3],     pa1h, pa1l);
                split2(s[2 * ks + 1][0], s[2 * ks + 1][1], pa2h, pa2l);
                split2(s[2 * ks + 1][2], s[2 * ks + 1][3], pa3h, pa3l);
                #pragma unroll
                for (int nt = 0; nt < 16; nt++) {
                    const int bo = (nt * 8 + grp) * VSW + hh * 32 + ks * 8 + qd;
                    const uint32_t bh0 = sVh[bo], bh1 = sVh[bo + 4];
                    const uint32_t bl0 = sVl[bo], bl1 = sVl[bo + 4];
                    mma_bf16(o[nt], pa0h, pa1h, pa2h, pa3h, bh0, bh1);
                    mma_bf16(o[nt], pa0h, pa1h, pa2h, pa3h, bl0, bl1);
                    mma_bf16(o[nt], pa0l, pa1l, pa2l, pa3l, bh0, bh1);
                }
            }
        }
    }

    const float i0 = 1.0f / l0, i1 = 1.0f / l1;
    const size_t ro0 = ((size_t)(bb * CS + q0 + rA)) * CE + h * CD;
    const size_t ro1 = ro0 + (size_t)8 * CE;
    #pragma unroll
    for (int nt = 0; nt < 16; nt++) {
        const int c = nt * 8 + 2 * qd;
        float2 w0, w1;
        w0.x = o[nt][0] * i0; w0.y = o[nt][1] * i0;
        w1.x = o[nt][2] * i1; w1.y = o[nt][3] * i1;
        *(float2*)&O[ro0 + c] = w0;
        *(float2*)&O[ro1 + c] = w1;
    }
}

// ---------------------------------------------------------------------------
// Launch
// ---------------------------------------------------------------------------
extern "C" void kernel_launch(void* const* d_in, const int* in_sizes, int n_in,
                              void* d_out, int out_size)
{
    (void)in_sizes; (void)n_in; (void)out_size;
    const float* x  = (const float*)d_in[0];
    const float* Wq = (const float*)d_in[1];
    const float* bq = (const float*)d_in[2];
    const float* Wk = (const float*)d_in[3];
    const float* bk = (const float*)d_in[4];
    const float* Wv = (const float*)d_in[5];
    const float* bv = (const float*)d_in[6];
    const float* Wo = (const float*)d_in[7];
    const float* bo = (const float*)d_in[8];
    const float* qn = (const float*)d_in[9];
    const float* kn = (const float*)d_in[10];
    float* out = (float*)d_out;

    float *q, *k, *v, *attn;
    cudaGetSymbolAddress((void**)&q,    g_q);
    cudaGetSymbolAddress((void**)&k,    g_k);
    cudaGetSymbolAddress((void**)&v,    g_v);
    cudaGetSymbolAddress((void**)&attn, g_attn);

    (void)cudaFuncSetAttribute(gemm_bf16x3_nt_bias,
                               cudaFuncAttributeMaxDynamicSharedMemorySize,
                               GEMM_SMEM);
    (void)cudaFuncSetAttribute(flash_attn_mma,
                               cudaFuncAttributeMaxDynamicSharedMemorySize,
                               FLASH_SMEM);

    dim3 gE(CE / 128, MROWS / 128);    // (16, 32)
    dim3 gKV(KVD / 128, MROWS / 128);  // (8, 32)

    gemm_bf16x3_nt_bias<<<gE, 256, GEMM_SMEM>>>(x, Wq, bq, q, CE, CE);
    gemm_bf16x3_nt_bias<<<gKV, 256, GEMM_SMEM>>>(x, Wk, bk, k, KVD, CE);
    gemm_bf16x3_nt_bias<<<gKV, 256, GEMM_SMEM>>>(x, Wv, bv, v, KVD, CE);

    rmsnorm_kernel<<<MROWS * CH, 128>>>(q, qn);
    rmsnorm_kernel<<<MROWS * CKV, 128>>>(k, kn);

    dim3 ga(CS / 128, CH, CB);         // (16, 16, 2)
    flash_attn_mma<<<ga, 256, FLASH_SMEM>>>(q, k, v, attn);

    gemm_bf16x3_nt_bias<<<gE, 256, GEMM_SMEM>>>(attn, Wo, bo, out, CE, CE);
}

// round 15
// speedup vs baseline: 1.3592x; 1.3592x over previous
#include <cuda_runtime.h>
#include <cuda_fp16.h>
#include <math.h>
#include <float.h>
#include <stdint.h>

// Problem constants
constexpr int CB  = 2;
constexpr int CS  = 2048;
constexpr int CE  = 2048;
constexpr int CH  = 16;
constexpr int CKV = 8;
constexpr int CD  = 128;
constexpr int MROWS = CB * CS;          // 4096
constexpr int KVD   = CKV * CD;         // 1024
constexpr float RMS_EPS = 1.1920928955078125e-07f;
constexpr float ATTN_SCALE = 0.08838834764831845f;  // 1/sqrt(128)

// Scratch (device globals; no runtime allocation allowed)
__device__ float g_q[MROWS * CE];
__device__ float g_k[MROWS * KVD];
__device__ float g_v[MROWS * KVD];
__device__ float g_attn[MROWS * CE];

// ---------------------------------------------------------------------------
// Helpers: fp16 pack / hi-lo split + fp16 mma.sync
// ---------------------------------------------------------------------------
__device__ __forceinline__ uint32_t pack2h(float a, float b)
{
    __half2 h = __floats2half2_rn(a, b);
    return *reinterpret_cast<uint32_t*>(&h);
}

__device__ __forceinline__ void split2h(float a, float b, uint32_t& hi, uint32_t& lo)
{
    __half ha = __float2half_rn(a), hb = __float2half_rn(b);
    float fa = __half2float(ha), fb = __half2float(hb);
    __half la = __float2half_rn(a - fa), lb = __float2half_rn(b - fb);
    hi = (uint32_t)__half_as_ushort(ha) | ((uint32_t)__half_as_ushort(hb) << 16);
    lo = (uint32_t)__half_as_ushort(la) | ((uint32_t)__half_as_ushort(lb) << 16);
}

__device__ __forceinline__ void mma_f16(float (&c)[4],
    uint32_t a0, uint32_t a1, uint32_t a2, uint32_t a3,
    uint32_t b0, uint32_t b1)
{
    asm volatile(
        "mma.sync.aligned.m16n8k16.row.col.f32.f16.f16.f32 "
        "{%0,%1,%2,%3},{%4,%5,%6,%7},{%8,%9},{%0,%1,%2,%3};"
        : "+f"(c[0]), "+f"(c[1]), "+f"(c[2]), "+f"(c[3])
        : "r"(a0), "r"(a1), "r"(a2), "r"(a3), "r"(b0), "r"(b1));
}

// ---------------------------------------------------------------------------
// fp16 2-pass GEMM: C[M,N] = A[M,K] @ W[N,K]^T + bias[N]
// A rounded to fp16 (hi only); W split hi/lo.  D = Ah*Wh + Ah*Wl.
// Block tile 128x128, BK=16, 256 threads (8 warps 2x4), warp tile 64x32.
// 2-stage smem, single __syncthreads per k-step.
// ---------------------------------------------------------------------------
constexpr int SW     = 12;              // smem row stride in words (8 used + 4 pad)
constexpr int TILEW  = 128 * SW;        // 1536 words per tile
constexpr int STAGEW = 3 * TILEW;       // Ah, Wh, Wl = 4608 words
constexpr int GEMM_SMEM = 2 * STAGEW * 4;  // 36864 B

__global__ __launch_bounds__(256) void gemm_f16x2_nt_bias(
    const float* __restrict__ A, const float* __restrict__ W,
    const float* __restrict__ bias, float* __restrict__ C,
    int Ndim, int Kdim)
{
    extern __shared__ uint32_t smw[];
    const int tid  = threadIdx.x;
    const int warp = tid >> 5, lane = tid & 31;
    const int wm = warp & 1, wn = warp >> 1;
    const int grp = lane >> 2, qd = lane & 3;
    const int row0 = blockIdx.y * 128;
    const int col0 = blockIdx.x * 128;

    const int ar = tid >> 2;             // 0..63 (rows ar, ar+64)
    const int kq = (tid & 3) << 2;       // 0,4,8,12
    const int kw = kq >> 1;              // word offset 0,2,4,6
    const float* Ap = A + (size_t)row0 * Kdim;
    const float* Wp = W + (size_t)col0 * Kdim;
    const int o0 = ar * SW + kw;
    const int o1 = (ar + 64) * SW + kw;

    float acc[4][4][4];
    #pragma unroll
    for (int i = 0; i < 4; i++)
        #pragma unroll
        for (int j = 0; j < 4; j++)
            #pragma unroll
            for (int c = 0; c < 4; c++) acc[i][j][c] = 0.f;

    const int NK = Kdim / 16;
    float4 ra0, ra1, rw0, rw1;

    // prologue: k-step 0 into stage 0
    ra0 = *(const float4*)&Ap[(size_t)ar * Kdim + kq];
    ra1 = *(const float4*)&Ap[(size_t)(ar + 64) * Kdim + kq];
    rw0 = *(const float4*)&Wp[(size_t)ar * Kdim + kq];
    rw1 = *(const float4*)&Wp[(size_t)(ar + 64) * Kdim + kq];
    {
        uint32_t* hA = smw;
        uint32_t* hW = smw + TILEW;
        uint32_t* lW = smw + 2 * TILEW;
        hA[o0] = pack2h(ra0.x, ra0.y); hA[o0 + 1] = pack2h(ra0.z, ra0.w);
        hA[o1] = pack2h(ra1.x, ra1.y); hA[o1 + 1] = pack2h(ra1.z, ra1.w);
        uint32_t h0, l0, h1, l1;
        split2h(rw0.x, rw0.y, h0, l0); split2h(rw0.z, rw0.w, h1, l1);
        hW[o0] = h0; hW[o0 + 1] = h1; lW[o0] = l0; lW[o0 + 1] = l1;
        split2h(rw1.x, rw1.y, h0, l0); split2h(rw1.z, rw1.w, h1, l1);
        hW[o1] = h0; hW[o1 + 1] = h1; lW[o1] = l0; lW[o1 + 1] = l1;
    }
    __syncthreads();

    for (int ks = 0; ks < NK; ks++) {
        // prefetch next k-step
        if (ks + 1 < NK) {
            const int k0 = (ks + 1) * 16;
            ra0 = *(const float4*)&Ap[(size_t)ar * Kdim + k0 + kq];
            ra1 = *(const float4*)&Ap[(size_t)(ar + 64) * Kdim + k0 + kq];
            rw0 = *(const float4*)&Wp[(size_t)ar * Kdim + k0 + kq];
            rw1 = *(const float4*)&Wp[(size_t)(ar + 64) * Kdim + k0 + kq];
        }

        // compute on stage ks&1
        {
            const uint32_t* st = smw + (ks & 1) * STAGEW;
            const uint32_t* uAh = st;
            const uint32_t* uWh = st + TILEW;
            const uint32_t* uWl = st + 2 * TILEW;

            uint32_t ah[4][4], bh[4][2], bl[4][2];
            #pragma unroll
            for (int mt = 0; mt < 4; mt++) {
                const int m = wm * 64 + mt * 16;
                const int a0o = (m + grp) * SW + qd;
                const int a1o = a0o + 8 * SW;
                ah[mt][0] = uAh[a0o]; ah[mt][1] = uAh[a1o];
                ah[mt][2] = uAh[a0o + 4]; ah[mt][3] = uAh[a1o + 4];
            }
            #pragma unroll
            for (int nt = 0; nt < 4; nt++) {
                const int bo = (wn * 32 + nt * 8 + grp) * SW + qd;
                bh[nt][0] = uWh[bo]; bh[nt][1] = uWh[bo + 4];
                bl[nt][0] = uWl[bo]; bl[nt][1] = uWl[bo + 4];
            }
            #pragma unroll
            for (int mt = 0; mt < 4; mt++)
                #pragma unroll
                for (int nt = 0; nt < 4; nt++)
                    mma_f16(acc[mt][nt], ah[mt][0], ah[mt][1], ah[mt][2], ah[mt][3],
                            bh[nt][0], bh[nt][1]);
            #pragma unroll
            for (int mt = 0; mt < 4; mt++)
                #pragma unroll
                for (int nt = 0; nt < 4; nt++)
                    mma_f16(acc[mt][nt], ah[mt][0], ah[mt][1], ah[mt][2], ah[mt][3],
                            bl[nt][0], bl[nt][1]);
        }

        // store prefetched k-step into the other stage
        if (ks + 1 < NK) {
            uint32_t* st = smw + ((ks + 1) & 1) * STAGEW;
            uint32_t* hA = st;
            uint32_t* hW = st + TILEW;
            uint32_t* lW = st + 2 * TILEW;
            hA[o0] = pack2h(ra0.x, ra0.y); hA[o0 + 1] = pack2h(ra0.z, ra0.w);
            hA[o1] = pack2h(ra1.x, ra1.y); hA[o1 + 1] = pack2h(ra1.z, ra1.w);
            uint32_t h0, l0, h1, l1;
            split2h(rw0.x, rw0.y, h0, l0); split2h(rw0.z, rw0.w, h1, l1);
            hW[o0] = h0; hW[o0 + 1] = h1; lW[o0] = l0; lW[o0 + 1] = l1;
            split2h(rw1.x, rw1.y, h0, l0); split2h(rw1.z, rw1.w, h1, l1);
            hW[o1] = h0; hW[o1 + 1] = h1; lW[o1] = l0; lW[o1 + 1] = l1;
        }
        __syncthreads();
    }

    #pragma unroll
    for (int mt = 0; mt < 4; mt++) {
        const int row = row0 + wm * 64 + mt * 16 + grp;
        #pragma unroll
        for (int nt = 0; nt < 4; nt++) {
            const int col = col0 + wn * 32 + nt * 8 + 2 * qd;
            const float b0 = bias[col], b1 = bias[col + 1];
            float2 v0, v1;
            v0.x = acc[mt][nt][0] + b0; v0.y = acc[mt][nt][1] + b1;
            v1.x = acc[mt][nt][2] + b0; v1.y = acc[mt][nt][3] + b1;
            *(float2*)&C[(size_t)row * Ndim + col] = v0;
            *(float2*)&C[(size_t)(row + 8) * Ndim + col] = v1;
        }
    }
}

// ---------------------------------------------------------------------------
// RMSNorm over contiguous 128-element segments.
// ---------------------------------------------------------------------------
__global__ __launch_bounds__(128) void rmsnorm_kernel(
    float* __restrict__ buf, const float* __restrict__ w)
{
    __shared__ float red[4];
    float* p = buf + (size_t)blockIdx.x * CD;
    const int t = threadIdx.x;
    float v = p[t];
    float sq = v * v;
    #pragma unroll
    for (int o = 16; o > 0; o >>= 1) sq += __shfl_xor_sync(0xffffffffu, sq, o);
    if ((t & 31) == 0) red[t >> 5] = sq;
    __syncthreads();
    float ms = (red[0] + red[1] + red[2] + red[3]) * (1.0f / 128.0f);
    p[t] = v * rsqrtf(ms + RMS_EPS) * w[t];
}

// ---------------------------------------------------------------------------
// Flash attention, fp16 2-pass. 128-query blocks, 128-key tiles (two 64-key
// halves). 256 threads, qt reversed. Q rounded (hi only); K,V split hi/lo;
// P rounded.  S = Qh*(Kh+Kl);  O += Ph*(Vh+Vl).
// ---------------------------------------------------------------------------
constexpr int QSW = 68;
constexpr int VSW = 68;
constexpr int OFF_QH = 0;
constexpr int OFF_KH = OFF_QH + 128 * QSW;   // 8704
constexpr int OFF_KL = OFF_KH + 128 * QSW;   // 17408
constexpr int OFF_VH = OFF_KL + 128 * QSW;   // 26112
constexpr int OFF_VL = OFF_VH + 128 * VSW;   // 34816
constexpr int FLASH_WORDS = OFF_VL + 128 * VSW;  // 43520
constexpr int FLASH_SMEM = FLASH_WORDS * 4;      // 174080 B

__global__ __launch_bounds__(256) void flash_attn_mma(
    const float* __restrict__ Q, const float* __restrict__ K,
    const float* __restrict__ V, float* __restrict__ O)
{
    extern __shared__ uint32_t swd[];
    uint32_t* sQh = swd + OFF_QH;
    uint32_t* sKh = swd + OFF_KH;
    uint32_t* sKl = swd + OFF_KL;
    uint32_t* sVh = swd + OFF_VH;
    uint32_t* sVl = swd + OFF_VL;

    const int qt = gridDim.x - 1 - blockIdx.x;   // heavy blocks first
    const int h  = blockIdx.y;
    const int bb = blockIdx.z;
    const int kvh = h >> 1;                      // G = 2
    const int tid = threadIdx.x;
    const int warp = tid >> 5, lane = tid & 31;
    const int grp = lane >> 2, qd = lane & 3;
    const int q0 = qt * 128;
    const int rA = warp * 16 + grp;

    // Q tile: 128 rows x 64 words, fp16 rounded
    for (int i = tid; i < 128 * 64; i += 256) {
        const int r = i >> 6, wd = i & 63;
        float2 f = *(const float2*)&Q[((size_t)(bb * CS + q0 + r)) * CE + h * CD + 2 * wd];
        sQh[r * QSW + wd] = pack2h(f.x, f.y);
    }

    float o[16][4];
    #pragma unroll
    for (int nt = 0; nt < 16; nt++)
        #pragma unroll
        for (int c = 0; c < 4; c++) o[nt][c] = 0.f;
    float m0 = -INFINITY, m1 = -INFINITY, l0 = 0.f, l1 = 0.f;

    const int nkt = qt + 1;

    for (int kt = 0; kt < nkt; kt++) {
        const int k0 = kt * 128;
        const bool diag = (kt == nkt - 1);
        __syncthreads();

        // K tile: split hi/lo
        for (int i = tid; i < 128 * 64; i += 256) {
            const int r = i >> 6, wd = i & 63;
            float2 f = *(const float2*)&K[((size_t)(bb * CS + k0 + r)) * KVD + kvh * CD + 2 * wd];
            split2h(f.x, f.y, sKh[r * QSW + wd], sKl[r * QSW + wd]);
        }
        // V tile transposed: word (d, j) packs keys (2j, 2j+1) at dim d
        for (int i = tid; i < 128 * 64; i += 256) {
            const int d = i & 127, j = i >> 7;
            const size_t base = ((size_t)(bb * CS + k0 + 2 * j)) * KVD + kvh * CD + d;
            split2h(V[base], V[base + KVD], sVh[d * VSW + j], sVl[d * VSW + j]);
        }
        __syncthreads();

        #pragma unroll
        for (int hh = 0; hh < 2; hh++) {
            // S = Qh @ (Kh + Kl)^T : 2 passes
            float s[8][4];
            #pragma unroll
            for (int nt = 0; nt < 8; nt++)
                #pragma unroll
                for (int c = 0; c < 4; c++) s[nt][c] = 0.f;

            #pragma unroll
            for (int ks = 0; ks < 8; ks++) {
                const int ao  = rA * QSW + ks * 8 + qd;
                const int a1o = ao + 8 * QSW;
                const uint32_t ah0 = sQh[ao],  ah1 = sQh[a1o];
                const uint32_t ah2 = sQh[ao + 4], ah3 = sQh[a1o + 4];
                #pragma unroll
                for (int nt = 0; nt < 8; nt++) {
                    const int bo = (hh * 64 + nt * 8 + grp) * QSW + ks * 8 + qd;
                    const uint32_t bh0 = sKh[bo], bh1 = sKh[bo + 4];
                    const uint32_t bl0 = sKl[bo], bl1 = sKl[bo + 4];
                    mma_f16(s[nt], ah0, ah1, ah2, ah3, bh0, bh1);
                    mma_f16(s[nt], ah0, ah1, ah2, ah3, bl0, bl1);
                }
            }

            // scale + causal mask (diagonal tile only)
            const int gr0 = q0 + rA, gr1 = gr0 + 8;
            if (diag) {
                #pragma unroll
                for (int nt = 0; nt < 8; nt++) {
                    const int gc = k0 + hh * 64 + nt * 8 + 2 * qd;
                    s[nt][0] = (gc     > gr0) ? -1e30f : s[nt][0] * ATTN_SCALE;
                    s[nt][1] = (gc + 1 > gr0) ? -1e30f : s[nt][1] * ATTN_SCALE;
                    s[nt][2] = (gc     > gr1) ? -1e30f : s[nt][2] * ATTN_SCALE;
                    s[nt][3] = (gc + 1 > gr1) ? -1e30f : s[nt][3] * ATTN_SCALE;
                }
            } else {
                #pragma unroll
                for (int nt = 0; nt < 8; nt++) {
                    s[nt][0] *= ATTN_SCALE; s[nt][1] *= ATTN_SCALE;
                    s[nt][2] *= ATTN_SCALE; s[nt][3] *= ATTN_SCALE;
                }
            }

            // online softmax (rows rA, rA+8)
            float mx0 = -INFINITY, mx1 = -INFINITY;
            #pragma unroll
            for (int nt = 0; nt < 8; nt++) {
                mx0 = fmaxf(mx0, fmaxf(s[nt][0], s[nt][1]));
                mx1 = fmaxf(mx1, fmaxf(s[nt][2], s[nt][3]));
            }
            mx0 = fmaxf(mx0, __shfl_xor_sync(0xffffffffu, mx0, 1));
            mx0 = fmaxf(mx0, __shfl_xor_sync(0xffffffffu, mx0, 2));
            mx1 = fmaxf(mx1, __shfl_xor_sync(0xffffffffu, mx1, 1));
            mx1 = fmaxf(mx1, __shfl_xor_sync(0xffffffffu, mx1, 2));
            const float mn0 = fmaxf(m0, mx0), mn1 = fmaxf(m1, mx1);
            const float c0 = __expf(m0 - mn0), c1 = __expf(m1 - mn1);
            float rs0 = 0.f, rs1 = 0.f;
            #pragma unroll
            for (int nt = 0; nt < 8; nt++) {
                s[nt][0] = __expf(s[nt][0] - mn0); rs0 += s[nt][0];
                s[nt][1] = __expf(s[nt][1] - mn0); rs0 += s[nt][1];
                s[nt][2] = __expf(s[nt][2] - mn1); rs1 += s[nt][2];
                s[nt][3] = __expf(s[nt][3] - mn1); rs1 += s[nt][3];
            }
            rs0 += __shfl_xor_sync(0xffffffffu, rs0, 1);
            rs0 += __shfl_xor_sync(0xffffffffu, rs0, 2);
            rs1 += __shfl_xor_sync(0xffffffffu, rs1, 1);
            rs1 += __shfl_xor_sync(0xffffffffu, rs1, 2);
            l0 = l0 * c0 + rs0; l1 = l1 * c1 + rs1;
            m0 = mn0; m1 = mn1;
            #pragma unroll
            for (int nt = 0; nt < 16; nt++) {
                o[nt][0] *= c0; o[nt][1] *= c0;
                o[nt][2] *= c1; o[nt][3] *= c1;
            }

            // O += Ph @ (Vh + Vl) : P rounded to fp16 in-register, 2 passes
            #pragma unroll
            for (int ks = 0; ks < 4; ks++) {
                const uint32_t pa0 = pack2h(s[2 * ks][0],     s[2 * ks][1]);
                const uint32_t pa1 = pack2h(s[2 * ks][2],     s[2 * ks][3]);
                const uint32_t pa2 = pack2h(s[2 * ks + 1][0], s[2 * ks + 1][1]);
                const uint32_t pa3 = pack2h(s[2 * ks + 1][2], s[2 * ks + 1][3]);
                #pragma unroll
                for (int nt = 0; nt < 16; nt++) {
                    const int bo = (nt * 8 + grp) * VSW + hh * 32 + ks * 8 + qd;
                    const uint32_t bh0 = sVh[bo], bh1 = sVh[bo + 4];
                    const uint32_t bl0 = sVl[bo], bl1 = sVl[bo + 4];
                    mma_f16(o[nt], pa0, pa1, pa2, pa3, bh0, bh1);
                    mma_f16(o[nt], pa0, pa1, pa2, pa3, bl0, bl1);
                }
            }
        }
    }

    const float i0 = 1.0f / l0, i1 = 1.0f / l1;
    const size_t ro0 = ((size_t)(bb * CS + q0 + rA)) * CE + h * CD;
    const size_t ro1 = ro0 + (size_t)8 * CE;
    #pragma unroll
    for (int nt = 0; nt < 16; nt++) {
        const int c = nt * 8 + 2 * qd;
        float2 w0, w1;
        w0.x = o[nt][0] * i0; w0.y = o[nt][1] * i0;
        w1.x = o[nt][2] * i1; w1.y = o[nt][3] * i1;
        *(float2*)&O[ro0 + c] = w0;
        *(float2*)&O[ro1 + c] = w1;
    }
}

// ---------------------------------------------------------------------------
// Launch
// ---------------------------------------------------------------------------
extern "C" void kernel_launch(void* const* d_in, const int* in_sizes, int n_in,
                              void* d_out, int out_size)
{
    (void)in_sizes; (void)n_in; (void)out_size;
    const float* x  = (const float*)d_in[0];
    const float* Wq = (const float*)d_in[1];
    const float* bq = (const float*)d_in[2];
    const float* Wk = (const float*)d_in[3];
    const float* bk = (const float*)d_in[4];
    const float* Wv = (const float*)d_in[5];
    const float* bv = (const float*)d_in[6];
    const float* Wo = (const float*)d_in[7];
    const float* bo = (const float*)d_in[8];
    const float* qn = (const float*)d_in[9];
    const float* kn = (const float*)d_in[10];
    float* out = (float*)d_out;

    float *q, *k, *v, *attn;
    cudaGetSymbolAddress((void**)&q,    g_q);
    cudaGetSymbolAddress((void**)&k,    g_k);
    cudaGetSymbolAddress((void**)&v,    g_v);
    cudaGetSymbolAddress((void**)&attn, g_attn);

    (void)cudaFuncSetAttribute(gemm_f16x2_nt_bias,
                               cudaFuncAttributeMaxDynamicSharedMemorySize,
                               GEMM_SMEM);
    (void)cudaFuncSetAttribute(flash_attn_mma,
                               cudaFuncAttributeMaxDynamicSharedMemorySize,
                               FLASH_SMEM);

    dim3 gE(CE / 128, MROWS / 128);    // (16, 32)
    dim3 gKV(KVD / 128, MROWS / 128);  // (8, 32)

    gemm_f16x2_nt_bias<<<gE, 256, GEMM_SMEM>>>(x, Wq, bq, q, CE, CE);
    gemm_f16x2_nt_bias<<<gKV, 256, GEMM_SMEM>>>(x, Wk, bk, k, KVD, CE);
    gemm_f16x2_nt_bias<<<gKV, 256, GEMM_SMEM>>>(x, Wv, bv, v, KVD, CE);

    rmsnorm_kernel<<<MROWS * CH, 128>>>(q, qn);
    rmsnorm_kernel<<<MROWS * CKV, 128>>>(k, kn);

    dim3 ga(CS / 128, CH, CB);         // (16, 16, 2)
    flash_attn_mma<<<ga, 256, FLASH_SMEM>>>(q, k, v, attn);

    gemm_f16x2_nt_bias<<<gE, 256, GEMM_SMEM>>>(attn, Wo, bo, out, CE, CE);
}

// round 16
// speedup vs baseline: 1.5352x; 1.1295x over previous
#include <cuda_runtime.h>
#include <cuda_fp16.h>
#include <math.h>
#include <float.h>
#include <stdint.h>

// Problem constants
constexpr int CB  = 2;
constexpr int CS  = 2048;
constexpr int CE  = 2048;
constexpr int CH  = 16;
constexpr int CKV = 8;
constexpr int CD  = 128;
constexpr int MROWS = CB * CS;          // 4096
constexpr int KVD   = CKV * CD;         // 1024
constexpr float RMS_EPS = 1.1920928955078125e-07f;
constexpr float ATTN_SCALE = 0.08838834764831845f;  // 1/sqrt(128)

// Scratch (device globals; no runtime allocation allowed)
__device__ float    g_q[MROWS * CE];
__device__ float    g_k[MROWS * KVD];
__device__ float    g_v[MROWS * KVD];
__device__ float    g_attn[MROWS * CE];
__device__ uint32_t g_qh[MROWS * CE / 2];                 // fp16x2 planes
__device__ uint32_t g_kh[MROWS * KVD / 2], g_kl[MROWS * KVD / 2];
__device__ uint32_t g_vth[CB * CKV * CD * CS / 2], g_vtl[CB * CKV * CD * CS / 2];

// ---------------------------------------------------------------------------
// Helpers: fp16 pack / hi-lo split + fp16 mma.sync
// ---------------------------------------------------------------------------
__device__ __forceinline__ uint32_t pack2h(float a, float b)
{
    __half2 h = __floats2half2_rn(a, b);
    return *reinterpret_cast<uint32_t*>(&h);
}

__device__ __forceinline__ void split2h(float a, float b, uint32_t& hi, uint32_t& lo)
{
    __half ha = __float2half_rn(a), hb = __float2half_rn(b);
    float fa = __half2float(ha), fb = __half2float(hb);
    __half la = __float2half_rn(a - fa), lb = __float2half_rn(b - fb);
    hi = (uint32_t)__half_as_ushort(ha) | ((uint32_t)__half_as_ushort(hb) << 16);
    lo = (uint32_t)__half_as_ushort(la) | ((uint32_t)__half_as_ushort(lb) << 16);
}

__device__ __forceinline__ void mma_f16(float (&c)[4],
    uint32_t a0, uint32_t a1, uint32_t a2, uint32_t a3,
    uint32_t b0, uint32_t b1)
{
    asm volatile(
        "mma.sync.aligned.m16n8k16.row.col.f32.f16.f16.f32 "
        "{%0,%1,%2,%3},{%4,%5,%6,%7},{%8,%9},{%0,%1,%2,%3};"
        : "+f"(c[0]), "+f"(c[1]), "+f"(c[2]), "+f"(c[3])
        : "r"(a0), "r"(a1), "r"(a2), "r"(a3), "r"(b0), "r"(b1));
}

// ---------------------------------------------------------------------------
// fp16 2-pass GEMM (R15, unchanged): C = A @ W^T + bias.
// A rounded to fp16; W split hi/lo.  D = Ah*Wh + Ah*Wl.
// ---------------------------------------------------------------------------
constexpr int SW     = 12;
constexpr int TILEW  = 128 * SW;
constexpr int STAGEW = 3 * TILEW;       // Ah, Wh, Wl
constexpr int GEMM_SMEM = 2 * STAGEW * 4;  // 36864 B

__global__ __launch_bounds__(256) void gemm_f16x2_nt_bias(
    const float* __restrict__ A, const float* __restrict__ W,
    const float* __restrict__ bias, float* __restrict__ C,
    int Ndim, int Kdim)
{
    extern __shared__ uint32_t smw[];
    const int tid  = threadIdx.x;
    const int warp = tid >> 5, lane = tid & 31;
    const int wm = warp & 1, wn = warp >> 1;
    const int grp = lane >> 2, qd = lane & 3;
    const int row0 = blockIdx.y * 128;
    const int col0 = blockIdx.x * 128;

    const int ar = tid >> 2;
    const int kq = (tid & 3) << 2;
    const int kw = kq >> 1;
    const float* Ap = A + (size_t)row0 * Kdim;
    const float* Wp = W + (size_t)col0 * Kdim;
    const int o0 = ar * SW + kw;
    const int o1 = (ar + 64) * SW + kw;

    float acc[4][4][4];
    #pragma unroll
    for (int i = 0; i < 4; i++)
        #pragma unroll
        for (int j = 0; j < 4; j++)
            #pragma unroll
            for (int c = 0; c < 4; c++) acc[i][j][c] = 0.f;

    const int NK = Kdim / 16;
    float4 ra0, ra1, rw0, rw1;

    ra0 = *(const float4*)&Ap[(size_t)ar * Kdim + kq];
    ra1 = *(const float4*)&Ap[(size_t)(ar + 64) * Kdim + kq];
    rw0 = *(const float4*)&Wp[(size_t)ar * Kdim + kq];
    rw1 = *(const float4*)&Wp[(size_t)(ar + 64) * Kdim + kq];
    {
        uint32_t* hA = smw;
        uint32_t* hW = smw + TILEW;
        uint32_t* lW = smw + 2 * TILEW;
        hA[o0] = pack2h(ra0.x, ra0.y); hA[o0 + 1] = pack2h(ra0.z, ra0.w);
        hA[o1] = pack2h(ra1.x, ra1.y); hA[o1 + 1] = pack2h(ra1.z, ra1.w);
        uint32_t h0, l0, h1, l1;
        split2h(rw0.x, rw0.y, h0, l0); split2h(rw0.z, rw0.w, h1, l1);
        hW[o0] = h0; hW[o0 + 1] = h1; lW[o0] = l0; lW[o0 + 1] = l1;
        split2h(rw1.x, rw1.y, h0, l0); split2h(rw1.z, rw1.w, h1, l1);
        hW[o1] = h0; hW[o1 + 1] = h1; lW[o1] = l0; lW[o1 + 1] = l1;
    }
    __syncthreads();

    for (int ks = 0; ks < NK; ks++) {
        if (ks + 1 < NK) {
            const int k0 = (ks + 1) * 16;
            ra0 = *(const float4*)&Ap[(size_t)ar * Kdim + k0 + kq];
            ra1 = *(const float4*)&Ap[(size_t)(ar + 64) * Kdim + k0 + kq];
            rw0 = *(const float4*)&Wp[(size_t)ar * Kdim + k0 + kq];
            rw1 = *(const float4*)&Wp[(size_t)(ar + 64) * Kdim + k0 + kq];
        }

        {
            const uint32_t* st = smw + (ks & 1) * STAGEW;
            const uint32_t* uAh = st;
            const uint32_t* uWh = st + TILEW;
            const uint32_t* uWl = st + 2 * TILEW;

            uint32_t ah[4][4], bh[4][2], bl[4][2];
            #pragma unroll
            for (int mt = 0; mt < 4; mt++) {
                const int m = wm * 64 + mt * 16;
                const int a0o = (m + grp) * SW + qd;
                const int a1o = a0o + 8 * SW;
                ah[mt][0] = uAh[a0o]; ah[mt][1] = uAh[a1o];
                ah[mt][2] = uAh[a0o + 4]; ah[mt][3] = uAh[a1o + 4];
            }
            #pragma unroll
            for (int nt = 0; nt < 4; nt++) {
                const int bo = (wn * 32 + nt * 8 + grp) * SW + qd;
                bh[nt][0] = uWh[bo]; bh[nt][1] = uWh[bo + 4];
                bl[nt][0] = uWl[bo]; bl[nt][1] = uWl[bo + 4];
            }
            #pragma unroll
            for (int mt = 0; mt < 4; mt++)
                #pragma unroll
                for (int nt = 0; nt < 4; nt++)
                    mma_f16(acc[mt][nt], ah[mt][0], ah[mt][1], ah[mt][2], ah[mt][3],
                            bh[nt][0], bh[nt][1]);
            #pragma unroll
            for (int mt = 0; mt < 4; mt++)
                #pragma unroll
                for (int nt = 0; nt < 4; nt++)
                    mma_f16(acc[mt][nt], ah[mt][0], ah[mt][1], ah[mt][2], ah[mt][3],
                            bl[nt][0], bl[nt][1]);
        }

        if (ks + 1 < NK) {
            uint32_t* st = smw + ((ks + 1) & 1) * STAGEW;
            uint32_t* hA = st;
            uint32_t* hW = st + TILEW;
            uint32_t* lW = st + 2 * TILEW;
            hA[o0] = pack2h(ra0.x, ra0.y); hA[o0 + 1] = pack2h(ra0.z, ra0.w);
            hA[o1] = pack2h(ra1.x, ra1.y); hA[o1 + 1] = pack2h(ra1.z, ra1.w);
            uint32_t h0, l0, h1, l1;
            split2h(rw0.x, rw0.y, h0, l0); split2h(rw0.z, rw0.w, h1, l1);
            hW[o0] = h0; hW[o0 + 1] = h1; lW[o0] = l0; lW[o0 + 1] = l1;
            split2h(rw1.x, rw1.y, h0, l0); split2h(rw1.z, rw1.w, h1, l1);
            hW[o1] = h0; hW[o1 + 1] = h1; lW[o1] = l0; lW[o1 + 1] = l1;
        }
        __syncthreads();
    }

    #pragma unroll
    for (int mt = 0; mt < 4; mt++) {
        const int row = row0 + wm * 64 + mt * 16 + grp;
        #pragma unroll
        for (int nt = 0; nt < 4; nt++) {
            const int col = col0 + wn * 32 + nt * 8 + 2 * qd;
            const float b0 = bias[col], b1 = bias[col + 1];
            float2 v0, v1;
            v0.x = acc[mt][nt][0] + b0; v0.y = acc[mt][nt][1] + b1;
            v1.x = acc[mt][nt][2] + b0; v1.y = acc[mt][nt][3] + b1;
            *(float2*)&C[(size_t)row * Ndim + col] = v0;
            *(float2*)&C[(size_t)(row + 8) * Ndim + col] = v1;
        }
    }
}

// ---------------------------------------------------------------------------
// RMSNorm fused with fp16 conversion.
//  - Q variant: rounds to fp16, writes hi plane only.
//  - K variant: splits hi/lo, writes both planes.
// One block per 128-elem segment; planes indexed segment*64 + word.
// ---------------------------------------------------------------------------
__global__ __launch_bounds__(128) void rmsnorm_pack_q(
    const float* __restrict__ buf, const float* __restrict__ w,
    uint32_t* __restrict__ qh)
{
    __shared__ float red[4];
    const float* p = buf + (size_t)blockIdx.x * CD;
    const int t = threadIdx.x;
    float v = p[t];
    float sq = v * v;
    #pragma unroll
    for (int o = 16; o > 0; o >>= 1) sq += __shfl_xor_sync(0xffffffffu, sq, o);
    if ((t & 31) == 0) red[t >> 5] = sq;
    __syncthreads();
    float ms = (red[0] + red[1] + red[2] + red[3]) * (1.0f / 128.0f);
    float nv = v * rsqrtf(ms + RMS_EPS) * w[t];
    float other = __shfl_xor_sync(0xffffffffu, nv, 1);
    if ((t & 1) == 0)
        qh[(size_t)blockIdx.x * 64 + (t >> 1)] = pack2h(nv, other);
}

__global__ __launch_bounds__(128) void rmsnorm_split_k(
    const float* __restrict__ buf, const float* __restrict__ w,
    uint32_t* __restrict__ kh, uint32_t* __restrict__ kl)
{
    __shared__ float red[4];
    const float* p = buf + (size_t)blockIdx.x * CD;
    const int t = threadIdx.x;
    float v = p[t];
    float sq = v * v;
    #pragma unroll
    for (int o = 16; o > 0; o >>= 1) sq += __shfl_xor_sync(0xffffffffu, sq, o);
    if ((t & 31) == 0) red[t >> 5] = sq;
    __syncthreads();
    float ms = (red[0] + red[1] + red[2] + red[3]) * (1.0f / 128.0f);
    float nv = v * rsqrtf(ms + RMS_EPS) * w[t];
    float other = __shfl_xor_sync(0xffffffffu, nv, 1);
    if ((t & 1) == 0) {
        uint32_t h, l;
        split2h(nv, other, h, l);
        const size_t wi = (size_t)blockIdx.x * 64 + (t >> 1);
        kh[wi] = h; kl[wi] = l;
    }
}

// ---------------------------------------------------------------------------
// V transpose + fp16 split: word vt[((bb*CKV+kvh)*CD + d)*(CS/2) + j]
// packs tokens (2j, 2j+1) at dim d.
// ---------------------------------------------------------------------------
__global__ __launch_bounds__(256) void vtrans_hl(
    const float* __restrict__ v, uint32_t* __restrict__ vth,
    uint32_t* __restrict__ vtl)
{
    __shared__ float tile[CD][65];
    const int t0  = blockIdx.x * 64;
    const int kvh = blockIdx.y;
    const int bb  = blockIdx.z;
    const int tid = threadIdx.x;

    #pragma unroll
    for (int it = 0; it < 8; it++) {
        const int idx = tid + it * 256;
        const int r = idx >> 5, dq = (idx & 31) * 4;
        float4 f = *(const float4*)&v[(size_t)(bb * CS + t0 + r) * KVD + kvh * CD + dq];
        tile[dq][r] = f.x; tile[dq + 1][r] = f.y;
        tile[dq + 2][r] = f.z; tile[dq + 3][r] = f.w;
    }
    __syncthreads();

    #pragma unroll
    for (int it = 0; it < 16; it++) {
        const int idx = tid + it * 256;
        const int d = idx >> 5, j = idx & 31;
        uint32_t h, l;
        split2h(tile[d][2 * j], tile[d][2 * j + 1], h, l);
        const size_t wi = ((size_t)((bb * CKV + kvh) * CD + d)) * (CS / 2) + (t0 >> 1) + j;
        vth[wi] = h; vtl[wi] = l;
    }
}

// ---------------------------------------------------------------------------
// Flash attention, fp16 2-pass on pre-split planes. 128-q blocks, 128-key
// tiles (two 64-key halves). 256 threads, qt reversed. Loaders: pure copies.
// ---------------------------------------------------------------------------
constexpr int QSW = 68;
constexpr int VSW = 68;
constexpr int OFF_QH = 0;
constexpr int OFF_KH = OFF_QH + 128 * QSW;   // 8704
constexpr int OFF_KL = OFF_KH + 128 * QSW;   // 17408
constexpr int OFF_VH = OFF_KL + 128 * QSW;   // 26112
constexpr int OFF_VL = OFF_VH + 128 * VSW;   // 34816
constexpr int FLASH_WORDS = OFF_VL + 128 * VSW;  // 43520
constexpr int FLASH_SMEM = FLASH_WORDS * 4;      // 174080 B

__global__ __launch_bounds__(256) void flash_attn_mma(
    const uint32_t* __restrict__ Qh, const uint32_t* __restrict__ Kh,
    const uint32_t* __restrict__ Kl, const uint32_t* __restrict__ Vth,
    const uint32_t* __restrict__ Vtl, float* __restrict__ O)
{
    extern __shared__ uint32_t swd[];
    uint32_t* sQh = swd + OFF_QH;
    uint32_t* sKh = swd + OFF_KH;
    uint32_t* sKl = swd + OFF_KL;
    uint32_t* sVh = swd + OFF_VH;
    uint32_t* sVl = swd + OFF_VL;

    const int qt = gridDim.x - 1 - blockIdx.x;   // heavy blocks first
    const int h  = blockIdx.y;
    const int bb = blockIdx.z;
    const int kvh = h >> 1;                      // G = 2
    const int tid = threadIdx.x;
    const int warp = tid >> 5, lane = tid & 31;
    const int grp = lane >> 2, qd = lane & 3;
    const int q0 = qt * 128;
    const int rA = warp * 16 + grp;

    // Q tile copy (128 rows x 64 words)
    for (int i = tid; i < 128 * 32; i += 256) {
        const int r = i >> 5, wp = (i & 31) * 2;
        const size_t src = (size_t)(bb * CS + q0 + r) * (CE / 2) + h * 64 + wp;
        *(uint2*)&sQh[r * QSW + wp] = *(const uint2*)&Qh[src];
    }

    float o[16][4];
    #pragma unroll
    for (int nt = 0; nt < 16; nt++)
        #pragma unroll
        for (int c = 0; c < 4; c++) o[nt][c] = 0.f;
    float m0 = -INFINITY, m1 = -INFINITY, l0 = 0.f, l1 = 0.f;

    const int nkt = qt + 1;

    for (int kt = 0; kt < nkt; kt++) {
        const int k0 = kt * 128;
        const bool diag = (kt == nkt - 1);
        __syncthreads();

        // K tile copy (128 rows x 64 words, both planes)
        for (int i = tid; i < 128 * 32; i += 256) {
            const int r = i >> 5, wp = (i & 31) * 2;
            const size_t src = (size_t)(bb * CS + k0 + r) * (KVD / 2) + kvh * 64 + wp;
            *(uint2*)&sKh[r * QSW + wp] = *(const uint2*)&Kh[src];
            *(uint2*)&sKl[r * QSW + wp] = *(const uint2*)&Kl[src];
        }
        // V tile copy (pre-transposed: 128 d-rows x 64 words, both planes)
        for (int i = tid; i < 128 * 32; i += 256) {
            const int d = i >> 5, jp = (i & 31) * 2;
            const size_t src = ((size_t)((bb * CKV + kvh) * CD + d)) * (CS / 2) + (k0 >> 1) + jp;
            *(uint2*)&sVh[d * VSW + jp] = *(const uint2*)&Vth[src];
            *(uint2*)&sVl[d * VSW + jp] = *(const uint2*)&Vtl[src];
        }
        __syncthreads();

        #pragma unroll
        for (int hh = 0; hh < 2; hh++) {
            // S = Qh @ (Kh + Kl)^T : 2 passes
            float s[8][4];
            #pragma unroll
            for (int nt = 0; nt < 8; nt++)
                #pragma unroll
                for (int c = 0; c < 4; c++) s[nt][c] = 0.f;

            #pragma unroll
            for (int ks = 0; ks < 8; ks++) {
                const int ao  = rA * QSW + ks * 8 + qd;
                const int a1o = ao + 8 * QSW;
                const uint32_t ah0 = sQh[ao],  ah1 = sQh[a1o];
                const uint32_t ah2 = sQh[ao + 4], ah3 = sQh[a1o + 4];
                #pragma unroll
                for (int nt = 0; nt < 8; nt++) {
                    const int bo = (hh * 64 + nt * 8 + grp) * QSW + ks * 8 + qd;
                    const uint32_t bh0 = sKh[bo], bh1 = sKh[bo + 4];
                    const uint32_t bl0 = sKl[bo], bl1 = sKl[bo + 4];
                    mma_f16(s[nt], ah0, ah1, ah2, ah3, bh0, bh1);
                    mma_f16(s[nt], ah0, ah1, ah2, ah3, bl0, bl1);
                }
            }

            // scale + causal mask (diagonal tile only)
            const int gr0 = q0 + rA, gr1 = gr0 + 8;
            if (diag) {
                #pragma unroll
                for (int nt = 0; nt < 8; nt++) {
                    const int gc = k0 + hh * 64 + nt * 8 + 2 * qd;
                    s[nt][0] = (gc     > gr0) ? -1e30f : s[nt][0] * ATTN_SCALE;
                    s[nt][1] = (gc + 1 > gr0) ? -1e30f : s[nt][1] * ATTN_SCALE;
                    s[nt][2] = (gc     > gr1) ? -1e30f : s[nt][2] * ATTN_SCALE;
                    s[nt][3] = (gc + 1 > gr1) ? -1e30f : s[nt][3] * ATTN_SCALE;
                }
            } else {
                #pragma unroll
                for (int nt = 0; nt < 8; nt++) {
                    s[nt][0] *= ATTN_SCALE; s[nt][1] *= ATTN_SCALE;
                    s[nt][2] *= ATTN_SCALE; s[nt][3] *= ATTN_SCALE;
                }
            }

            // online softmax (rows rA, rA+8)
            float mx0 = -INFINITY, mx1 = -INFINITY;
            #pragma unroll
            for (int nt = 0; nt < 8; nt++) {
                mx0 = fmaxf(mx0, fmaxf(s[nt][0], s[nt][1]));
                mx1 = fmaxf(mx1, fmaxf(s[nt][2], s[nt][3]));
            }
            mx0 = fmaxf(mx0, __shfl_xor_sync(0xffffffffu, mx0, 1));
            mx0 = fmaxf(mx0, __shfl_xor_sync(0xffffffffu, mx0, 2));
            mx1 = fmaxf(mx1, __shfl_xor_sync(0xffffffffu, mx1, 1));
            mx1 = fmaxf(mx1, __shfl_xor_sync(0xffffffffu, mx1, 2));
            const float mn0 = fmaxf(m0, mx0), mn1 = fmaxf(m1, mx1);
            const float c0 = __expf(m0 - mn0), c1 = __expf(m1 - mn1);
            float rs0 = 0.f, rs1 = 0.f;
            #pragma unroll
            for (int nt = 0; nt < 8; nt++) {
                s[nt][0] = __expf(s[nt][0] - mn0); rs0 += s[nt][0];
                s[nt][1] = __expf(s[nt][1] - mn0); rs0 += s[nt][1];
                s[nt][2] = __expf(s[nt][2] - mn1); rs1 += s[nt][2];
                s[nt][3] = __expf(s[nt][3] - mn1); rs1 += s[nt][3];
            }
            rs0 += __shfl_xor_sync(0xffffffffu, rs0, 1);
            rs0 += __shfl_xor_sync(0xffffffffu, rs0, 2);
            rs1 += __shfl_xor_sync(0xffffffffu, rs1, 1);
            rs1 += __shfl_xor_sync(0xffffffffu, rs1, 2);
            l0 = l0 * c0 + rs0; l1 = l1 * c1 + rs1;
            m0 = mn0; m1 = mn1;
            #pragma unroll
            for (int nt = 0; nt < 16; nt++) {
                o[nt][0] *= c0; o[nt][1] *= c0;
                o[nt][2] *= c1; o[nt][3] *= c1;
            }

            // O += Ph @ (Vh + Vl) : P rounded to fp16 in-register, 2 passes
            #pragma unroll
            for (int ks = 0; ks < 4; ks++) {
                const uint32_t pa0 = pack2h(s[2 * ks][0],     s[2 * ks][1]);
                const uint32_t pa1 = pack2h(s[2 * ks][2],     s[2 * ks][3]);
                const uint32_t pa2 = pack2h(s[2 * ks + 1][0], s[2 * ks + 1][1]);
                const uint32_t pa3 = pack2h(s[2 * ks + 1][2], s[2 * ks + 1][3]);
                #pragma unroll
                for (int nt = 0; nt < 16; nt++) {
                    const int bo = (nt * 8 + grp) * VSW + hh * 32 + ks * 8 + qd;
                    const uint32_t bh0 = sVh[bo], bh1 = sVh[bo + 4];
                    const uint32_t bl0 = sVl[bo], bl1 = sVl[bo + 4];
                    mma_f16(o[nt], pa0, pa1, pa2, pa3, bh0, bh1);
                    mma_f16(o[nt], pa0, pa1, pa2, pa3, bl0, bl1);
                }
            }
        }
    }

    const float i0 = 1.0f / l0, i1 = 1.0f / l1;
    const size_t ro0 = ((size_t)(bb * CS + q0 + rA)) * CE + h * CD;
    const size_t ro1 = ro0 + (size_t)8 * CE;
    #pragma unroll
    for (int nt = 0; nt < 16; nt++) {
        const int c = nt * 8 + 2 * qd;
        float2 w0, w1;
        w0.x = o[nt][0] * i0; w0.y = o[nt][1] * i0;
        w1.x = o[nt][2] * i1; w1.y = o[nt][3] * i1;
        *(float2*)&O[ro0 + c] = w0;
        *(float2*)&O[ro1 + c] = w1;
    }
}

// ---------------------------------------------------------------------------
// Launch
// ---------------------------------------------------------------------------
extern "C" void kernel_launch(void* const* d_in, const int* in_sizes, int n_in,
                              void* d_out, int out_size)
{
    (void)in_sizes; (void)n_in; (void)out_size;
    const float* x  = (const float*)d_in[0];
    const float* Wq = (const float*)d_in[1];
    const float* bq = (const float*)d_in[2];
    const float* Wk = (const float*)d_in[3];
    const float* bk = (const float*)d_in[4];
    const float* Wv = (const float*)d_in[5];
    const float* bv = (const float*)d_in[6];
    const float* Wo = (const float*)d_in[7];
    const float* bo = (const float*)d_in[8];
    const float* qn = (const float*)d_in[9];
    const float* kn = (const float*)d_in[10];
    float* out = (float*)d_out;

    float *q, *k, *v, *attn;
    uint32_t *qh, *kh, *kl, *vth, *vtl;
    cudaGetSymbolAddress((void**)&q,    g_q);
    cudaGetSymbolAddress((void**)&k,    g_k);
    cudaGetSymbolAddress((void**)&v,    g_v);
    cudaGetSymbolAddress((void**)&attn, g_attn);
    cudaGetSymbolAddress((void**)&qh,   g_qh);
    cudaGetSymbolAddress((void**)&kh,   g_kh);
    cudaGetSymbolAddress((void**)&kl,   g_kl);
    cudaGetSymbolAddress((void**)&vth,  g_vth);
    cudaGetSymbolAddress((void**)&vtl,  g_vtl);

    (void)cudaFuncSetAttribute(gemm_f16x2_nt_bias,
                               cudaFuncAttributeMaxDynamicSharedMemorySize,
                               GEMM_SMEM);
    (void)cudaFuncSetAttribute(flash_attn_mma,
                               cudaFuncAttributeMaxDynamicSharedMemorySize,
                               FLASH_SMEM);

    dim3 gE(CE / 128, MROWS / 128);    // (16, 32)
    dim3 gKV(KVD / 128, MROWS / 128);  // (8, 32)

    gemm_f16x2_nt_bias<<<gE, 256, GEMM_SMEM>>>(x, Wq, bq, q, CE, CE);
    gemm_f16x2_nt_bias<<<gKV, 256, GEMM_SMEM>>>(x, Wk, bk, k, KVD, CE);
    gemm_f16x2_nt_bias<<<gKV, 256, GEMM_SMEM>>>(x, Wv, bv, v, KVD, CE);

    rmsnorm_pack_q<<<MROWS * CH, 128>>>(q, qn, qh);
    rmsnorm_split_k<<<MROWS * CKV, 128>>>(k, kn, kh, kl);

    dim3 gvt(CS / 64, CKV, CB);
    vtrans_hl<<<gvt, 256>>>(v, vth, vtl);

    dim3 ga(CS / 128, CH, CB);         // (16, 16, 2)
    flash_attn_mma<<<ga, 256, FLASH_SMEM>>>(qh, kh, kl, vth, vtl, attn);

    gemm_f16x2_nt_bias<<<gE, 256, GEMM_SMEM>>>(attn, Wo, bo, out, CE, CE);
}

// round 17
// speedup vs baseline: 1.9640x; 1.2794x over previous
#include <cuda_runtime.h>
#include <cuda_fp16.h>
#include <math.h>
#include <float.h>
#include <stdint.h>

// Problem constants
constexpr int CB  = 2;
constexpr int CS  = 2048;
constexpr int CE  = 2048;
constexpr int CH  = 16;
constexpr int CKV = 8;
constexpr int CD  = 128;
constexpr int MROWS = CB * CS;          // 4096
constexpr int KVD   = CKV * CD;         // 1024
constexpr float RMS_EPS = 1.1920928955078125e-07f;
constexpr float ATTN_SCALE = 0.08838834764831845f;  // 1/sqrt(128)

// Scratch (device globals; no runtime allocation allowed)
__device__ float    g_q[MROWS * CE];
__device__ float    g_k[MROWS * KVD];
__device__ float    g_v[MROWS * KVD];
__device__ float    g_attn[MROWS * CE];
__device__ uint32_t g_qh[MROWS * CE / 2];          // fp16x2 planes (hi only)
__device__ uint32_t g_kh[MROWS * KVD / 2];
__device__ uint32_t g_vth[CB * CKV * CD * CS / 2];

// ---------------------------------------------------------------------------
// Helpers: fp16 pack + fp16 mma.sync
// ---------------------------------------------------------------------------
__device__ __forceinline__ uint32_t pack2h(float a, float b)
{
    __half2 h = __floats2half2_rn(a, b);
    return *reinterpret_cast<uint32_t*>(&h);
}

__device__ __forceinline__ void mma_f16(float (&c)[4],
    uint32_t a0, uint32_t a1, uint32_t a2, uint32_t a3,
    uint32_t b0, uint32_t b1)
{
    asm volatile(
        "mma.sync.aligned.m16n8k16.row.col.f32.f16.f16.f32 "
        "{%0,%1,%2,%3},{%4,%5,%6,%7},{%8,%9},{%0,%1,%2,%3};"
        : "+f"(c[0]), "+f"(c[1]), "+f"(c[2]), "+f"(c[3])
        : "r"(a0), "r"(a1), "r"(a2), "r"(a3), "r"(b0), "r"(b1));
}

// ---------------------------------------------------------------------------
// fp16 1-pass GEMM: C[M,N] = A[M,K] @ W[N,K]^T + bias[N]
// Both operands rounded to fp16.  Block 128x128, BK=16, 256 threads,
// warp tile 64x32, 2-stage smem, single __syncthreads per k-step.
// ---------------------------------------------------------------------------
constexpr int SW     = 12;              // smem row stride in words (8 used + 4 pad)
constexpr int TILEW  = 128 * SW;        // 1536 words per tile
constexpr int STAGEW = 2 * TILEW;       // Ah, Wh
constexpr int GEMM_SMEM = 2 * STAGEW * 4;  // 24576 B

__global__ __launch_bounds__(256) void gemm_f16_nt_bias(
    const float* __restrict__ A, const float* __restrict__ W,
    const float* __restrict__ bias, float* __restrict__ C,
    int Ndim, int Kdim)
{
    extern __shared__ uint32_t smw[];
    const int tid  = threadIdx.x;
    const int warp = tid >> 5, lane = tid & 31;
    const int wm = warp & 1, wn = warp >> 1;
    const int grp = lane >> 2, qd = lane & 3;
    const int row0 = blockIdx.y * 128;
    const int col0 = blockIdx.x * 128;

    const int ar = tid >> 2;
    const int kq = (tid & 3) << 2;
    const int kw = kq >> 1;
    const float* Ap = A + (size_t)row0 * Kdim;
    const float* Wp = W + (size_t)col0 * Kdim;
    const int o0 = ar * SW + kw;
    const int o1 = (ar + 64) * SW + kw;

    float acc[4][4][4];
    #pragma unroll
    for (int i = 0; i < 4; i++)
        #pragma unroll
        for (int j = 0; j < 4; j++)
            #pragma unroll
            for (int c = 0; c < 4; c++) acc[i][j][c] = 0.f;

    const int NK = Kdim / 16;
    float4 ra0, ra1, rw0, rw1;

    // prologue: k-step 0 into stage 0
    ra0 = *(const float4*)&Ap[(size_t)ar * Kdim + kq];
    ra1 = *(const float4*)&Ap[(size_t)(ar + 64) * Kdim + kq];
    rw0 = *(const float4*)&Wp[(size_t)ar * Kdim + kq];
    rw1 = *(const float4*)&Wp[(size_t)(ar + 64) * Kdim + kq];
    {
        uint32_t* hA = smw;
        uint32_t* hW = smw + TILEW;
        hA[o0] = pack2h(ra0.x, ra0.y); hA[o0 + 1] = pack2h(ra0.z, ra0.w);
        hA[o1] = pack2h(ra1.x, ra1.y); hA[o1 + 1] = pack2h(ra1.z, ra1.w);
        hW[o0] = pack2h(rw0.x, rw0.y); hW[o0 + 1] = pack2h(rw0.z, rw0.w);
        hW[o1] = pack2h(rw1.x, rw1.y); hW[o1 + 1] = pack2h(rw1.z, rw1.w);
    }
    __syncthreads();

    for (int ks = 0; ks < NK; ks++) {
        if (ks + 1 < NK) {
            const int k0 = (ks + 1) * 16;
            ra0 = *(const float4*)&Ap[(size_t)ar * Kdim + k0 + kq];
            ra1 = *(const float4*)&Ap[(size_t)(ar + 64) * Kdim + k0 + kq];
            rw0 = *(const float4*)&Wp[(size_t)ar * Kdim + k0 + kq];
            rw1 = *(const float4*)&Wp[(size_t)(ar + 64) * Kdim + k0 + kq];
        }

        {
            const uint32_t* st = smw + (ks & 1) * STAGEW;
            const uint32_t* uAh = st;
            const uint32_t* uWh = st + TILEW;

            uint32_t ah[4][4], bh[4][2];
            #pragma unroll
            for (int mt = 0; mt < 4; mt++) {
                const int m = wm * 64 + mt * 16;
                const int a0o = (m + grp) * SW + qd;
                const int a1o = a0o + 8 * SW;
                ah[mt][0] = uAh[a0o]; ah[mt][1] = uAh[a1o];
                ah[mt][2] = uAh[a0o + 4]; ah[mt][3] = uAh[a1o + 4];
            }
            #pragma unroll
            for (int nt = 0; nt < 4; nt++) {
                const int bo = (wn * 32 + nt * 8 + grp) * SW + qd;
                bh[nt][0] = uWh[bo]; bh[nt][1] = uWh[bo + 4];
            }
            #pragma unroll
            for (int mt = 0; mt < 4; mt++)
                #pragma unroll
                for (int nt = 0; nt < 4; nt++)
                    mma_f16(acc[mt][nt], ah[mt][0], ah[mt][1], ah[mt][2], ah[mt][3],
                            bh[nt][0], bh[nt][1]);
        }

        if (ks + 1 < NK) {
            uint32_t* st = smw + ((ks + 1) & 1) * STAGEW;
            uint32_t* hA = st;
            uint32_t* hW = st + TILEW;
            hA[o0] = pack2h(ra0.x, ra0.y); hA[o0 + 1] = pack2h(ra0.z, ra0.w);
            hA[o1] = pack2h(ra1.x, ra1.y); hA[o1 + 1] = pack2h(ra1.z, ra1.w);
            hW[o0] = pack2h(rw0.x, rw0.y); hW[o0 + 1] = pack2h(rw0.z, rw0.w);
            hW[o1] = pack2h(rw1.x, rw1.y); hW[o1 + 1] = pack2h(rw1.z, rw1.w);
        }
        __syncthreads();
    }

    #pragma unroll
    for (int mt = 0; mt < 4; mt++) {
        const int row = row0 + wm * 64 + mt * 16 + grp;
        #pragma unroll
        for (int nt = 0; nt < 4; nt++) {
            const int col = col0 + wn * 32 + nt * 8 + 2 * qd;
            const float b0 = bias[col], b1 = bias[col + 1];
            float2 v0, v1;
            v0.x = acc[mt][nt][0] + b0; v0.y = acc[mt][nt][1] + b1;
            v1.x = acc[mt][nt][2] + b0; v1.y = acc[mt][nt][3] + b1;
            *(float2*)&C[(size_t)row * Ndim + col] = v0;
            *(float2*)&C[(size_t)(row + 8) * Ndim + col] = v1;
        }
    }
}

// ---------------------------------------------------------------------------
// RMSNorm fused with fp16 rounding -> single hi plane (used for Q and K).
// ---------------------------------------------------------------------------
__global__ __launch_bounds__(128) void rmsnorm_pack(
    const float* __restrict__ buf, const float* __restrict__ w,
    uint32_t* __restrict__ outh)
{
    __shared__ float red[4];
    const float* p = buf + (size_t)blockIdx.x * CD;
    const int t = threadIdx.x;
    float v = p[t];
    float sq = v * v;
    #pragma unroll
    for (int o = 16; o > 0; o >>= 1) sq += __shfl_xor_sync(0xffffffffu, sq, o);
    if ((t & 31) == 0) red[t >> 5] = sq;
    __syncthreads();
    float ms = (red[0] + red[1] + red[2] + red[3]) * (1.0f / 128.0f);
    float nv = v * rsqrtf(ms + RMS_EPS) * w[t];
    float other = __shfl_xor_sync(0xffffffffu, nv, 1);
    if ((t & 1) == 0)
        outh[(size_t)blockIdx.x * 64 + (t >> 1)] = pack2h(nv, other);
}

// ---------------------------------------------------------------------------
// V transpose + fp16 rounding: word vt[((bb*CKV+kvh)*CD + d)*(CS/2) + j]
// packs tokens (2j, 2j+1) at dim d.
// ---------------------------------------------------------------------------
__global__ __launch_bounds__(256) void vtrans_h(
    const float* __restrict__ v, uint32_t* __restrict__ vth)
{
    __shared__ float tile[CD][65];
    const int t0  = blockIdx.x * 64;
    const int kvh = blockIdx.y;
    const int bb  = blockIdx.z;
    const int tid = threadIdx.x;

    #pragma unroll
    for (int it = 0; it < 8; it++) {
        const int idx = tid + it * 256;
        const int r = idx >> 5, dq = (idx & 31) * 4;
        float4 f = *(const float4*)&v[(size_t)(bb * CS + t0 + r) * KVD + kvh * CD + dq];
        tile[dq][r] = f.x; tile[dq + 1][r] = f.y;
        tile[dq + 2][r] = f.z; tile[dq + 3][r] = f.w;
    }
    __syncthreads();

    #pragma unroll
    for (int it = 0; it < 16; it++) {
        const int idx = tid + it * 256;
        const int d = idx >> 5, j = idx & 31;
        const size_t wi = ((size_t)((bb * CKV + kvh) * CD + d)) * (CS / 2) + (t0 >> 1) + j;
        vth[wi] = pack2h(tile[d][2 * j], tile[d][2 * j + 1]);
    }
}

// ---------------------------------------------------------------------------
// Flash attention, fp16 1-pass on pre-packed planes. 128-q blocks, 128-key
// tiles (two 64-key halves). 256 threads, qt reversed. smem 104 KB -> 2 CTAs/SM.
// ---------------------------------------------------------------------------
constexpr int QSW = 68;
constexpr int VSW = 68;
constexpr int OFF_QH = 0;
constexpr int OFF_KH = OFF_QH + 128 * QSW;   // 8704
constexpr int OFF_VH = OFF_KH + 128 * QSW;   // 17408
constexpr int FLASH_WORDS = OFF_VH + 128 * VSW;  // 26112
constexpr int FLASH_SMEM = FLASH_WORDS * 4;      // 104448 B

__global__ __launch_bounds__(256) void flash_attn_mma(
    const uint32_t* __restrict__ Qh, const uint32_t* __restrict__ Kh,
    const uint32_t* __restrict__ Vth, float* __restrict__ O)
{
    extern __shared__ uint32_t swd[];
    uint32_t* sQh = swd + OFF_QH;
    uint32_t* sKh = swd + OFF_KH;
    uint32_t* sVh = swd + OFF_VH;

    const int qt = gridDim.x - 1 - blockIdx.x;   // heavy blocks first
    const int h  = blockIdx.y;
    const int bb = blockIdx.z;
    const int kvh = h >> 1;                      // G = 2
    const int tid = threadIdx.x;
    const int warp = tid >> 5, lane = tid & 31;
    const int grp = lane >> 2, qd = lane & 3;
    const int q0 = qt * 128;
    const int rA = warp * 16 + grp;

    // Q tile copy (128 rows x 64 words)
    for (int i = tid; i < 128 * 32; i += 256) {
        const int r = i >> 5, wp = (i & 31) * 2;
        const size_t src = (size_t)(bb * CS + q0 + r) * (CE / 2) + h * 64 + wp;
        *(uint2*)&sQh[r * QSW + wp] = *(const uint2*)&Qh[src];
    }

    float o[16][4];
    #pragma unroll
    for (int nt = 0; nt < 16; nt++)
        #pragma unroll
        for (int c = 0; c < 4; c++) o[nt][c] = 0.f;
    float m0 = -INFINITY, m1 = -INFINITY, l0 = 0.f, l1 = 0.f;

    const int nkt = qt + 1;

    for (int kt = 0; kt < nkt; kt++) {
        const int k0 = kt * 128;
        const bool diag = (kt == nkt - 1);
        __syncthreads();

        // K tile copy (128 rows x 64 words)
        for (int i = tid; i < 128 * 32; i += 256) {
            const int r = i >> 5, wp = (i & 31) * 2;
            const size_t src = (size_t)(bb * CS + k0 + r) * (KVD / 2) + kvh * 64 + wp;
            *(uint2*)&sKh[r * QSW + wp] = *(const uint2*)&Kh[src];
        }
        // V tile copy (pre-transposed: 128 d-rows x 64 words)
        for (int i = tid; i < 128 * 32; i += 256) {
            const int d = i >> 5, jp = (i & 31) * 2;
            const size_t src = ((size_t)((bb * CKV + kvh) * CD + d)) * (CS / 2) + (k0 >> 1) + jp;
            *(uint2*)&sVh[d * VSW + jp] = *(const uint2*)&Vth[src];
        }
        __syncthreads();

        #pragma unroll
        for (int hh = 0; hh < 2; hh++) {
            // S = Qh @ Kh^T : 1 pass
            float s[8][4];
            #pragma unroll
            for (int nt = 0; nt < 8; nt++)
                #pragma unroll
                for (int c = 0; c < 4; c++) s[nt][c] = 0.f;

            #pragma unroll
            for (int ks = 0; ks < 8; ks++) {
                const int ao  = rA * QSW + ks * 8 + qd;
                const int a1o = ao + 8 * QSW;
                const uint32_t ah0 = sQh[ao],  ah1 = sQh[a1o];
                const uint32_t ah2 = sQh[ao + 4], ah3 = sQh[a1o + 4];
                #pragma unroll
                for (int nt = 0; nt < 8; nt++) {
                    const int bo = (hh * 64 + nt * 8 + grp) * QSW + ks * 8 + qd;
                    mma_f16(s[nt], ah0, ah1, ah2, ah3, sKh[bo], sKh[bo + 4]);
                }
            }

            // scale + causal mask (diagonal tile only)
            const int gr0 = q0 + rA, gr1 = gr0 + 8;
            if (diag) {
                #pragma unroll
                for (int nt = 0; nt < 8; nt++) {
                    const int gc = k0 + hh * 64 + nt * 8 + 2 * qd;
                    s[nt][0] = (gc     > gr0) ? -1e30f : s[nt][0] * ATTN_SCALE;
                    s[nt][1] = (gc + 1 > gr0) ? -1e30f : s[nt][1] * ATTN_SCALE;
                    s[nt][2] = (gc     > gr1) ? -1e30f : s[nt][2] * ATTN_SCALE;
                    s[nt][3] = (gc + 1 > gr1) ? -1e30f : s[nt][3] * ATTN_SCALE;
                }
            } else {
                #pragma unroll
                for (int nt = 0; nt < 8; nt++) {
                    s[nt][0] *= ATTN_SCALE; s[nt][1] *= ATTN_SCALE;
                    s[nt][2] *= ATTN_SCALE; s[nt][3] *= ATTN_SCALE;
                }
            }

            // online softmax (rows rA, rA+8)
            float mx0 = -INFINITY, mx1 = -INFINITY;
            #pragma unroll
            for (int nt = 0; nt < 8; nt++) {
                mx0 = fmaxf(mx0, fmaxf(s[nt][0], s[nt][1]));
                mx1 = fmaxf(mx1, fmaxf(s[nt][2], s[nt][3]));
            }
            mx0 = fmaxf(mx0, __shfl_xor_sync(0xffffffffu, mx0, 1));
            mx0 = fmaxf(mx0, __shfl_xor_sync(0xffffffffu, mx0, 2));
            mx1 = fmaxf(mx1, __shfl_xor_sync(0xffffffffu, mx1, 1));
            mx1 = fmaxf(mx1, __shfl_xor_sync(0xffffffffu, mx1, 2));
            const float mn0 = fmaxf(m0, mx0), mn1 = fmaxf(m1, mx1);
            const float c0 = __expf(m0 - mn0), c1 = __expf(m1 - mn1);
            float rs0 = 0.f, rs1 = 0.f;
            #pragma unroll
            for (int nt = 0; nt < 8; nt++) {
                s[nt][0] = __expf(s[nt][0] - mn0); rs0 += s[nt][0];
                s[nt][1] = __expf(s[nt][1] - mn0); rs0 += s[nt][1];
                s[nt][2] = __expf(s[nt][2] - mn1); rs1 += s[nt][2];
                s[nt][3] = __expf(s[nt][3] - mn1); rs1 += s[nt][3];
            }
            rs0 += __shfl_xor_sync(0xffffffffu, rs0, 1);
            rs0 += __shfl_xor_sync(0xffffffffu, rs0, 2);
            rs1 += __shfl_xor_sync(0xffffffffu, rs1, 1);
            rs1 += __shfl_xor_sync(0xffffffffu, rs1, 2);
            l0 = l0 * c0 + rs0; l1 = l1 * c1 + rs1;
            m0 = mn0; m1 = mn1;
            #pragma unroll
            for (int nt = 0; nt < 16; nt++) {
                o[nt][0] *= c0; o[nt][1] *= c0;
                o[nt][2] *= c1; o[nt][3] *= c1;
            }

            // O += Ph @ Vh : P rounded in-register, 1 pass
            #pragma unroll
            for (int ks = 0; ks < 4; ks++) {
                const uint32_t pa0 = pack2h(s[2 * ks][0],     s[2 * ks][1]);
                const uint32_t pa1 = pack2h(s[2 * ks][2],     s[2 * ks][3]);
                const uint32_t pa2 = pack2h(s[2 * ks + 1][0], s[2 * ks + 1][1]);
                const uint32_t pa3 = pack2h(s[2 * ks + 1][2], s[2 * ks + 1][3]);
                #pragma unroll
                for (int nt = 0; nt < 16; nt++) {
                    const int bo = (nt * 8 + grp) * VSW + hh * 32 + ks * 8 + qd;
                    mma_f16(o[nt], pa0, pa1, pa2, pa3, sVh[bo], sVh[bo + 4]);
                }
            }
        }
    }

    const float i0 = 1.0f / l0, i1 = 1.0f / l1;
    const size_t ro0 = ((size_t)(bb * CS + q0 + rA)) * CE + h * CD;
    const size_t ro1 = ro0 + (size_t)8 * CE;
    #pragma unroll
    for (int nt = 0; nt < 16; nt++) {
        const int c = nt * 8 + 2 * qd;
        float2 w0, w1;
        w0.x = o[nt][0] * i0; w0.y = o[nt][1] * i0;
        w1.x = o[nt][2] * i1; w1.y = o[nt][3] * i1;
        *(float2*)&O[ro0 + c] = w0;
        *(float2*)&O[ro1 + c] = w1;
    }
}

// ---------------------------------------------------------------------------
// Launch
// ---------------------------------------------------------------------------
extern "C" void kernel_launch(void* const* d_in, const int* in_sizes, int n_in,
                              void* d_out, int out_size)
{
    (void)in_sizes; (void)n_in; (void)out_size;
    const float* x  = (const float*)d_in[0];
    const float* Wq = (const float*)d_in[1];
    const float* bq = (const float*)d_in[2];
    const float* Wk = (const float*)d_in[3];
    const float* bk = (const float*)d_in[4];
    const float* Wv = (const float*)d_in[5];
    const float* bv = (const float*)d_in[6];
    const float* Wo = (const float*)d_in[7];
    const float* bo = (const float*)d_in[8];
    const float* qn = (const float*)d_in[9];
    const float* kn = (const float*)d_in[10];
    float* out = (float*)d_out;

    float *q, *k, *v, *attn;
    uint32_t *qh, *kh, *vth;
    cudaGetSymbolAddress((void**)&q,    g_q);
    cudaGetSymbolAddress((void**)&k,    g_k);
    cudaGetSymbolAddress((void**)&v,    g_v);
    cudaGetSymbolAddress((void**)&attn, g_attn);
    cudaGetSymbolAddress((void**)&qh,   g_qh);
    cudaGetSymbolAddress((void**)&kh,   g_kh);
    cudaGetSymbolAddress((void**)&vth,  g_vth);

    (void)cudaFuncSetAttribute(gemm_f16_nt_bias,
                               cudaFuncAttributeMaxDynamicSharedMemorySize,
                               GEMM_SMEM);
    (void)cudaFuncSetAttribute(flash_attn_mma,
                               cudaFuncAttributeMaxDynamicSharedMemorySize,
                               FLASH_SMEM);

    dim3 gE(CE / 128, MROWS / 128);    // (16, 32)
    dim3 gKV(KVD / 128, MROWS / 128);  // (8, 32)

    gemm_f16_nt_bias<<<gE, 256, GEMM_SMEM>>>(x, Wq, bq, q, CE, CE);
    gemm_f16_nt_bias<<<gKV, 256, GEMM_SMEM>>>(x, Wk, bk, k, KVD, CE);
    gemm_f16_nt_bias<<<gKV, 256, GEMM_SMEM>>>(x, Wv, bv, v, KVD, CE);

    rmsnorm_pack<<<MROWS * CH, 128>>>(q, qn, qh);
    rmsnorm_pack<<<MROWS * CKV, 128>>>(k, kn, kh);

    dim3 gvt(CS / 64, CKV, CB);
    vtrans_h<<<gvt, 256>>>(v, vth);

    dim3 ga(CS / 128, CH, CB);         // (16, 16, 2)
    flash_attn_mma<<<ga, 256, FLASH_SMEM>>>(qh, kh, vth, attn);

    gemm_f16_nt_bias<<<gE, 256, GEMM_SMEM>>>(attn, Wo, bo, out, CE, CE);
}